// round 3
// baseline (speedup 1.0000x reference)
#include <cuda_runtime.h>
#include <cuda_bf16.h>
#include <stdint.h>

// Problem constants
#define BATCH   1024
#define NFEAT   256
#define NSAMP   100000
// Tiling
#define BTILE   256                     // batch rows per CTA
#define FSUB    32                      // feature rows per subtile (100000 % 32 == 0 -> no masking)
#define NSUBT   (NSAMP / FSUB)          // 3125
#define FGROUPS 37                      // 37 * 4 = 148 CTAs = exactly one wave
#define SUBT_PG ((NSUBT + FGROUPS - 1) / FGROUPS)   // 85
#define BCHUNKS (BATCH / BTILE)         // 4

#define ASTRIDE 264                     // halves per smem row (+8 pad -> conflict-free ldmatrix)
#define A_BYTES (BTILE * ASTRIDE * 2)   // 135168
#define B_BYTES (FSUB * ASTRIDE * 2)    // 16896
#define SMEM_BYTES (A_BYTES + 2 * B_BYTES)  // 168960

#define CSCALE 28.853900817779268f      // (1/0.05) * log2(e): folded into bf16 A
#define LN2F   0.6931471805599453f

__device__ float2 g_part[FGROUPS * BATCH];
__device__ float  g_tgt[BATCH];

// Fast exp2 on the FFMA pipe (valid for t <= 0; clamped below -126).
// Magic-constant round-to-nearest + degree-5 Taylor for 2^f on [-0.5, 0.5].
__device__ __forceinline__ float exp2c(float t) {
    t = fmaxf(t, -126.0f);
    float tj = t + 12582912.0f;           // 1.5 * 2^23
    float fi = tj - 12582912.0f;          // round(t)
    float f  = t - fi;                    // [-0.5, 0.5]
    float p  = 0.0013333558f;
    p = fmaf(p, f, 0.0096181291f);
    p = fmaf(p, f, 0.0555041087f);
    p = fmaf(p, f, 0.2402265070f);
    p = fmaf(p, f, 0.6931471806f);
    p = fmaf(p, f, 1.0f);
    int ei = __float_as_int(tj) << 23;    // integer part into exponent field
    return __int_as_float(__float_as_int(p) + ei);
}

__device__ __forceinline__ void ldsm4(uint32_t& r0, uint32_t& r1, uint32_t& r2, uint32_t& r3,
                                      uint32_t addr) {
    asm volatile("ldmatrix.sync.aligned.m8n8.x4.shared.b16 {%0,%1,%2,%3}, [%4];"
                 : "=r"(r0), "=r"(r1), "=r"(r2), "=r"(r3) : "r"(addr));
}

__device__ __forceinline__ void mma16816(float* d, const uint32_t* a, const uint32_t* b) {
    asm volatile("mma.sync.aligned.m16n8k16.row.col.f32.bf16.bf16.f32 "
                 "{%0,%1,%2,%3}, {%4,%5,%6,%7}, {%8,%9}, {%0,%1,%2,%3};"
                 : "+f"(d[0]), "+f"(d[1]), "+f"(d[2]), "+f"(d[3])
                 : "r"(a[0]), "r"(a[1]), "r"(a[2]), "r"(a[3]), "r"(b[0]), "r"(b[1]));
}

// ---------------------------------------------------------------------------
// Main fused GEMM + online log2-softmax partials kernel.
// grid = (FGROUPS, BCHUNKS), 256 threads, 1 CTA/SM.
// ---------------------------------------------------------------------------
__global__ void __launch_bounds__(256, 1)
ce_main(const float* __restrict__ inputs, const float* __restrict__ features)
{
    extern __shared__ char smem[];
    const int tid  = threadIdx.x;
    const int lane = tid & 31;
    const int wid  = tid >> 5;
    const int g      = blockIdx.x;
    const int bchunk = blockIdx.y;

    // ---- load + convert A tile (256x256 fp32 -> bf16, prescaled by CSCALE) ----
    {
        const float4* inp4 = (const float4*)(inputs + (size_t)bchunk * BTILE * NFEAT);
        #pragma unroll
        for (int i = 0; i < 64; i++) {
            int idx = tid + i * 256;
            int row = idx >> 6, c4 = idx & 63;
            float4 v = inp4[idx];
            __nv_bfloat162 p0, p1;
            p0.x = __float2bfloat16_rn(v.x * CSCALE);
            p0.y = __float2bfloat16_rn(v.y * CSCALE);
            p1.x = __float2bfloat16_rn(v.z * CSCALE);
            p1.y = __float2bfloat16_rn(v.w * CSCALE);
            uint2 u;
            u.x = *(uint32_t*)&p0;
            u.y = *(uint32_t*)&p1;
            *(uint2*)(smem + row * (ASTRIDE * 2) + c4 * 8) = u;
        }
    }

    const uint32_t smem_u = (uint32_t)__cvta_generic_to_shared(smem);
    // ldmatrix per-thread addressing (x4 layouts)
    const int rA = wid * 32 + (lane & 7) + ((lane >> 3) & 1) * 8;
    const int kA = (lane >> 4) * 8;
    const uint32_t aBase = smem_u + (rA * ASTRIDE + kA) * 2;
    const int rB = lane & 7;
    const int kB = (lane >> 3) * 8;
    const uint32_t bOff = (rB * ASTRIDE + kB) * 2;
    const uint32_t bBuf0 = smem_u + A_BYTES;

    float rm[2][2] = {{-1e30f, -1e30f}, {-1e30f, -1e30f}};
    float rs[2][2] = {{0.f, 0.f}, {0.f, 0.f}};

    const int s0 = g * SUBT_PG;
    const int s1 = min(s0 + SUBT_PG, NSUBT);

    float4 stage[8];
    // prologue: stage + store subtile s0 into buffer 0
    {
        const float4* f4 = (const float4*)(features + (size_t)s0 * FSUB * NFEAT);
        #pragma unroll
        for (int i = 0; i < 8; i++) stage[i] = f4[tid + i * 256];
        #pragma unroll
        for (int i = 0; i < 8; i++) {
            int idx = tid + i * 256;
            int row = idx >> 6, c4 = idx & 63;
            __nv_bfloat162 p0, p1;
            p0.x = __float2bfloat16_rn(stage[i].x);
            p0.y = __float2bfloat16_rn(stage[i].y);
            p1.x = __float2bfloat16_rn(stage[i].z);
            p1.y = __float2bfloat16_rn(stage[i].w);
            uint2 u;
            u.x = *(uint32_t*)&p0;
            u.y = *(uint32_t*)&p1;
            *(uint2*)(smem + A_BYTES + row * (ASTRIDE * 2) + c4 * 8) = u;
        }
    }

    for (int s = s0; s < s1; s++) {
        const int cur = (s - s0) & 1;
        const bool hn = (s + 1) < s1;
        if (hn) {  // prefetch next subtile into registers (hides DRAM/L2 latency)
            const float4* f4 = (const float4*)(features + (size_t)(s + 1) * FSUB * NFEAT);
            #pragma unroll
            for (int i = 0; i < 8; i++) stage[i] = f4[tid + i * 256];
        }
        __syncthreads();   // buf[cur] fully written; buf[cur^1] fully consumed

        const uint32_t bb = bBuf0 + cur * B_BYTES + bOff;

        float acc[2][4][4];
        #pragma unroll
        for (int mi = 0; mi < 2; mi++)
            #pragma unroll
            for (int ni = 0; ni < 4; ni++)
                #pragma unroll
                for (int e = 0; e < 4; e++) acc[mi][ni][e] = 0.f;

        #pragma unroll
        for (int kk = 0; kk < 8; kk++) {
            uint32_t a[2][2][4];
            #pragma unroll
            for (int mi = 0; mi < 2; mi++)
                #pragma unroll
                for (int ks = 0; ks < 2; ks++)
                    ldsm4(a[mi][ks][0], a[mi][ks][1], a[mi][ks][2], a[mi][ks][3],
                          aBase + mi * (16 * ASTRIDE * 2) + (kk * 32 + ks * 16) * 2);
            uint32_t b[4][2][2];
            #pragma unroll
            for (int ni = 0; ni < 4; ni++) {
                uint32_t r0, r1, r2, r3;
                ldsm4(r0, r1, r2, r3, bb + ni * (8 * ASTRIDE * 2) + kk * 64);
                b[ni][0][0] = r0; b[ni][0][1] = r1;
                b[ni][1][0] = r2; b[ni][1][1] = r3;
            }
            #pragma unroll
            for (int ks = 0; ks < 2; ks++)
                #pragma unroll
                for (int mi = 0; mi < 2; mi++)
                    #pragma unroll
                    for (int ni = 0; ni < 4; ni++)
                        mma16816(acc[mi][ni], a[mi][ks], b[ni][ks]);
        }

        // online softmax update (base-2 domain), per-thread lazy state
        #pragma unroll
        for (int mi = 0; mi < 2; mi++)
            #pragma unroll
            for (int h = 0; h < 2; h++) {
                float v0 = acc[mi][0][h*2], v1 = acc[mi][0][h*2+1];
                float v2 = acc[mi][1][h*2], v3 = acc[mi][1][h*2+1];
                float v4 = acc[mi][2][h*2], v5 = acc[mi][2][h*2+1];
                float v6 = acc[mi][3][h*2], v7 = acc[mi][3][h*2+1];
                float tmax = fmaxf(fmaxf(fmaxf(v0, v1), fmaxf(v2, v3)),
                                   fmaxf(fmaxf(v4, v5), fmaxf(v6, v7)));
                float m  = rm[mi][h];
                float nm = fmaxf(m, tmax);
                float sum = exp2c(v0 - nm) + exp2c(v1 - nm)
                          + exp2c(v2 - nm) + exp2c(v3 - nm)
                          + exp2c(v4 - nm) + exp2c(v5 - nm)
                          + exp2c(v6 - nm) + exp2c(v7 - nm);
                rs[mi][h] = rs[mi][h] * exp2c(m - nm) + sum;
                rm[mi][h] = nm;
            }

        if (hn) {  // store next subtile into the other buffer
            char* dst = smem + A_BYTES + ((cur ^ 1) * B_BYTES);
            #pragma unroll
            for (int i = 0; i < 8; i++) {
                int idx = tid + i * 256;
                int row = idx >> 6, c4 = idx & 63;
                __nv_bfloat162 p0, p1;
                p0.x = __float2bfloat16_rn(stage[i].x);
                p0.y = __float2bfloat16_rn(stage[i].y);
                p1.x = __float2bfloat16_rn(stage[i].z);
                p1.y = __float2bfloat16_rn(stage[i].w);
                uint2 u;
                u.x = *(uint32_t*)&p0;
                u.y = *(uint32_t*)&p1;
                *(uint2*)(dst + row * (ASTRIDE * 2) + c4 * 8) = u;
            }
        }
    }

    // combine the 4 lanes owning each row, write partial (m, s)
    #pragma unroll
    for (int mi = 0; mi < 2; mi++)
        #pragma unroll
        for (int h = 0; h < 2; h++) {
            float m = rm[mi][h], sv = rs[mi][h];
            #pragma unroll
            for (int d = 1; d <= 2; d <<= 1) {
                float mo = __shfl_xor_sync(0xffffffffu, m, d);
                float so = __shfl_xor_sync(0xffffffffu, sv, d);
                float nm = fmaxf(m, mo);
                sv = sv * exp2c(m - nm) + so * exp2c(mo - nm);
                m = nm;
            }
            if ((lane & 3) == 0) {
                int row = bchunk * BTILE + wid * 32 + mi * 16 + h * 8 + (lane >> 2);
                g_part[g * BATCH + row] = make_float2(m, sv);
            }
        }
}

// ---------------------------------------------------------------------------
// Exact fp32 target logits: g_tgt[b] = 20 * dot(inputs[b], features[targets[b]])
// Handles targets stored as int32 or int64 (detected from zero high words).
// ---------------------------------------------------------------------------
__global__ void __launch_bounds__(256)
tgt_kernel(const float* __restrict__ inputs, const float* __restrict__ features,
           const int* __restrict__ t32)
{
    const int lane = threadIdx.x & 31;
    const int wid  = threadIdx.x >> 5;
    const int row  = blockIdx.x * 8 + wid;

    // int64 detection: if the data is int64, every odd 32-bit word (high half)
    // of the first 512 words is zero. Reads stay within the smaller (int32) size.
    int ok = 1;
    #pragma unroll
    for (int j = 0; j < 8; j++) ok &= (t32[1 + 2 * (lane + 32 * j)] == 0);
    const int is64 = __all_sync(0xffffffffu, ok);

    const int tgt = is64 ? t32[2 * row] : t32[row];
    const float* x = inputs + (size_t)row * NFEAT;
    const float* f = features + (size_t)tgt * NFEAT;
    float sum = 0.f;
    #pragma unroll
    for (int k = lane; k < NFEAT; k += 32) sum = fmaf(x[k], f[k], sum);
    #pragma unroll
    for (int d = 16; d; d >>= 1) sum += __shfl_xor_sync(0xffffffffu, sum, d);
    if (lane == 0) g_tgt[row] = sum * 20.0f;
}

// ---------------------------------------------------------------------------
// Final merge: combine 37 partials per row, lse in nats, mean NLL.
// ---------------------------------------------------------------------------
__global__ void __launch_bounds__(1024)
ce_final(float* __restrict__ out)
{
    __shared__ float red[1024];
    const int b = threadIdx.x;

    float M = g_part[b].x;
    #pragma unroll 1
    for (int gi = 1; gi < FGROUPS; gi++) M = fmaxf(M, g_part[gi * BATCH + b].x);
    float S = 0.f;
    #pragma unroll 1
    for (int gi = 0; gi < FGROUPS; gi++) {
        float2 p = g_part[gi * BATCH + b];
        S += p.y * exp2c(p.x - M);
    }
    float lse = (M + log2f(S)) * LN2F;   // natural-log LSE
    red[b] = lse - g_tgt[b];
    __syncthreads();
    #pragma unroll 1
    for (int st = 512; st; st >>= 1) {
        if (b < st) red[b] += red[b + st];
        __syncthreads();
    }
    if (b == 0) out[0] = red[0] * (1.0f / BATCH);
}

// ---------------------------------------------------------------------------
extern "C" void kernel_launch(void* const* d_in, const int* in_sizes, int n_in,
                              void* d_out, int out_size)
{
    // Resolve pointers by element count (robust to metadata ordering):
    // inputs: 1024*256 = 262144, targets: 1024, features: 100000*256 = 25600000
    const float* inputs   = nullptr;
    const int*   targets  = nullptr;
    const float* features = nullptr;
    for (int i = 0; i < n_in; i++) {
        if (in_sizes[i] == BATCH * NFEAT)      inputs   = (const float*)d_in[i];
        else if (in_sizes[i] == BATCH)         targets  = (const int*)d_in[i];
        else if (in_sizes[i] == NSAMP * NFEAT) features = (const float*)d_in[i];
    }

    cudaFuncSetAttribute(ce_main, cudaFuncAttributeMaxDynamicSharedMemorySize, SMEM_BYTES);

    tgt_kernel<<<BATCH / 8, 256>>>(inputs, features, targets);
    ce_main<<<dim3(FGROUPS, BCHUNKS), 256, SMEM_BYTES>>>(inputs, features);
    ce_final<<<1, 1024>>>((float*)d_out);
}